// round 5
// baseline (speedup 1.0000x reference)
#include <cuda_runtime.h>

#define BSZ 64
#define NSEQ 4096
#define DM 64
#define NSL 7
#define HH 128
#define CH 16          // chunks of N per batch for attention
#define LN_EPS 1e-5f
#define ATT_EPS 1e-8f

// ---------------- scratch (static device allocations are the sanctioned path) ----
__device__ float g_K[BSZ * NSEQ * DM];            // 67 MB
__device__ float g_V[BSZ * NSEQ * DM];            // 67 MB
__device__ float g_Q[BSZ * NSL * DM];
__device__ float g_slots[BSZ * NSL * DM];
__device__ float g_Up[BSZ * CH * NSL * DM];
__device__ float g_Sp[BSZ * CH * NSL];

// ---------------- packed f32x2 helpers (sm_103a FFMA2 path) ---------------------
__device__ __forceinline__ unsigned long long pk2(float lo, float hi) {
    unsigned long long r;
    asm("mov.b64 %0, {%1,%2};" : "=l"(r) : "f"(lo), "f"(hi));
    return r;
}
__device__ __forceinline__ void upk2(unsigned long long v, float &lo, float &hi) {
    asm("mov.b64 {%0,%1}, %2;" : "=f"(lo), "=f"(hi) : "l"(v));
}
__device__ __forceinline__ void ffma2(unsigned long long &d, unsigned long long a,
                                      unsigned long long b) {
    asm("fma.rn.f32x2 %0, %1, %2, %0;" : "+l"(d) : "l"(a), "l"(b));
}

// =================================================================================
// Kernel A: fused LayerNorm(inputs) + K/V projection.
// grid = 4096 blocks (64 rows each), 128 threads.
// Thread tile: rows r = ty + 16kp (+8), cols c = tx + 16j; FFMA2 packs row-pairs.
// Smem stride 68: LDS.128 at 4-aligned offsets -> conflict-free per quarter-warp.
// =================================================================================
__global__ void __launch_bounds__(128) proj_kv(
    const float* __restrict__ x, const float* __restrict__ Wk, const float* __restrict__ bk,
    const float* __restrict__ Wv, const float* __restrict__ bv,
    const float* __restrict__ g, const float* __restrict__ be)
{
    extern __shared__ float sm[];
    float* xs  = sm;               // 64*68
    float* ws  = xs + 64 * 68;     // 128*68 (Wk rows 0..63, Wv rows 64..127)
    float* rm  = ws + 128 * 68;    // 64
    float* ri  = rm + 64;          // 64
    float* gs  = ri + 64;          // 64
    float* bes = gs + 64;          // 64
    float* bkv = bes + 64;         // 128

    const int tid = threadIdx.x;
    const int rowbase = blockIdx.x * 64;

    // vectorized loads: weights (2048 float4) and x tile (1024 float4)
    {
        const float4* wk4 = (const float4*)Wk;
        const float4* wv4 = (const float4*)Wv;
        #pragma unroll
        for (int q = 0; q < 16; q++) {
            int i = tid + 128 * q;            // float4 index, 0..2047
            int r = i >> 4, d = (i & 15) * 4;
            float4 v = (i < 1024) ? wk4[i] : wv4[i - 1024];
            *(float4*)&ws[r * 68 + d] = v;
        }
        const float4* xg = (const float4*)(x + rowbase * 64);
        #pragma unroll
        for (int q = 0; q < 8; q++) {
            int i = tid + 128 * q;            // 0..1023
            int r = i >> 4, d = (i & 15) * 4;
            *(float4*)&xs[r * 68 + d] = xg[i];
        }
    }
    if (tid < 64) {
        gs[tid] = g[tid]; bes[tid] = be[tid];
        bkv[tid] = bk[tid]; bkv[64 + tid] = bv[tid];
    }
    __syncthreads();

    {   // row stats: 2 threads per row
        int r = tid >> 1, h = tid & 1;
        float s = 0.f, sq = 0.f;
        const float* row = &xs[r * 68 + h * 32];
        #pragma unroll
        for (int d = 0; d < 32; d++) { float v = row[d]; s += v; sq += v * v; }
        s  += __shfl_xor_sync(0xffffffffu, s, 1);
        sq += __shfl_xor_sync(0xffffffffu, sq, 1);
        if (h == 0) {
            float m = s * (1.f / 64.f);
            float var = sq * (1.f / 64.f) - m * m;
            rm[r] = m; ri[r] = rsqrtf(var + LN_EPS);
        }
    }
    __syncthreads();
    for (int i = tid; i < 4096; i += 128) {
        int r = i >> 6, d = i & 63;
        xs[r * 68 + d] = (xs[r * 68 + d] - rm[r]) * ri[r] * gs[d] + bes[d];
    }
    __syncthreads();

    const int tx = tid & 15, ty = tid >> 4;
    unsigned long long acc[4][8];   // [row-pair][j] : {row ty+16kp, row ty+16kp+8}
    #pragma unroll
    for (int kp = 0; kp < 4; kp++)
        #pragma unroll
        for (int j = 0; j < 8; j++) acc[kp][j] = 0ull;

    #pragma unroll 2
    for (int d = 0; d < 64; d += 4) {
        unsigned long long aa[4][4];   // [kp][e]
        #pragma unroll
        for (int kp = 0; kp < 4; kp++) {
            float4 a0 = *(const float4*)&xs[(ty + 16 * kp) * 68 + d];
            float4 a1 = *(const float4*)&xs[(ty + 16 * kp + 8) * 68 + d];
            aa[kp][0] = pk2(a0.x, a1.x);
            aa[kp][1] = pk2(a0.y, a1.y);
            aa[kp][2] = pk2(a0.z, a1.z);
            aa[kp][3] = pk2(a0.w, a1.w);
        }
        #pragma unroll
        for (int j = 0; j < 8; j++) {
            float4 b4 = *(const float4*)&ws[(tx + 16 * j) * 68 + d];
            unsigned long long bb;
            bb = pk2(b4.x, b4.x);
            #pragma unroll
            for (int kp = 0; kp < 4; kp++) ffma2(acc[kp][j], aa[kp][0], bb);
            bb = pk2(b4.y, b4.y);
            #pragma unroll
            for (int kp = 0; kp < 4; kp++) ffma2(acc[kp][j], aa[kp][1], bb);
            bb = pk2(b4.z, b4.z);
            #pragma unroll
            for (int kp = 0; kp < 4; kp++) ffma2(acc[kp][j], aa[kp][2], bb);
            bb = pk2(b4.w, b4.w);
            #pragma unroll
            for (int kp = 0; kp < 4; kp++) ffma2(acc[kp][j], aa[kp][3], bb);
        }
    }

    #pragma unroll
    for (int kp = 0; kp < 4; kp++) {
        #pragma unroll
        for (int j = 0; j < 8; j++) {
            float lo, hi; upk2(acc[kp][j], lo, hi);
            int c = tx + 16 * j;
            int r0 = rowbase + ty + 16 * kp;
            int r1 = r0 + 8;
            float bias = bkv[c];
            float v0 = lo + bias, v1 = hi + bias;
            if (c < 64) {
                g_K[r0 * 64 + c] = v0;
                g_K[r1 * 64 + c] = v1;
            } else {
                g_V[r0 * 64 + (c - 64)] = v0;
                g_V[r1 * 64 + (c - 64)] = v1;
            }
        }
    }
}

// =================================================================================
// Kernel B: slots init (mu + sigma*noise) + LN + first q projection. 64 blocks.
// =================================================================================
__global__ void __launch_bounds__(256) init_kernel(
    const float* __restrict__ noise, const float* __restrict__ mu,
    const float* __restrict__ sigma, const float* __restrict__ Wq,
    const float* __restrict__ bq, const float* __restrict__ g_sl,
    const float* __restrict__ be_sl)
{
    __shared__ float sl[448];
    __shared__ float ss[448];
    __shared__ float Wqs[64 * 65];
    const int tid = threadIdx.x, b = blockIdx.x;

    for (int i = tid; i < 448; i += 256) {
        int d = i & 63;
        float v = mu[d] + sigma[d] * noise[b * 448 + i];
        sl[i] = v;
        g_slots[b * 448 + i] = v;
    }
    for (int i = tid; i < 4096; i += 256) Wqs[(i >> 6) * 65 + (i & 63)] = Wq[i];
    __syncthreads();

    const int wi = tid >> 5, c = tid & 31;
    if (wi < 7) {
        float x0 = sl[wi * 64 + c], x1 = sl[wi * 64 + c + 32];
        float s = x0 + x1, sq = x0 * x0 + x1 * x1;
        #pragma unroll
        for (int o = 16; o > 0; o >>= 1) {
            s  += __shfl_xor_sync(0xffffffffu, s, o);
            sq += __shfl_xor_sync(0xffffffffu, sq, o);
        }
        float m = s * (1.f / 64.f);
        float var = sq * (1.f / 64.f) - m * m;
        float rin = rsqrtf(var + LN_EPS);
        ss[wi * 64 + c]      = (x0 - m) * rin * g_sl[c]      + be_sl[c];
        ss[wi * 64 + c + 32] = (x1 - m) * rin * g_sl[c + 32] + be_sl[c + 32];
    }
    __syncthreads();

    for (int idx = tid; idx < 448; idx += 256) {
        int i = idx >> 6, o = idx & 63;
        float acc = bq[o];
        const float* srow = &ss[i * 64];
        const float* wrow = &Wqs[o * 65];
        #pragma unroll 16
        for (int d = 0; d < 64; d++) acc += srow[d] * wrow[d];
        g_Q[b * 448 + idx] = acc;
    }
}

// =================================================================================
// Kernel C: streaming attention with register double-buffer prefetch.
// grid = (CH, B), 256 threads. Warp i (<7) owns slot i; lane c owns channels
// c and c+32. Softmax over slots is local per position; renorm deferred via S.
// =================================================================================
__global__ void __launch_bounds__(256) attn_kernel()
{
    __shared__ float qs[7 * 64];
    __shared__ float ks[64 * 65];
    __shared__ float vs[64 * 65];
    __shared__ float at[7 * 64];

    const int tid = threadIdx.x;
    const int b = blockIdx.y, ch = blockIdx.x;
    const int wi = tid >> 5, c = tid & 31;

    for (int i = tid; i < 448; i += 256) qs[i] = g_Q[b * 448 + i];

    float U0 = 0.f, U1 = 0.f, Sa = 0.f;
    const int base = (b * 4096 + ch * 256) * 64;
    const float4* Kg = (const float4*)(g_K + base);
    const float4* Vg = (const float4*)(g_V + base);

    // prefetch tile 0 into registers (4 float4 per array per thread)
    float4 rk[4], rv[4];
    #pragma unroll
    for (int q = 0; q < 4; q++) {
        rk[q] = Kg[tid + 256 * q];
        rv[q] = Vg[tid + 256 * q];
    }

    for (int t = 0; t < 4; t++) {
        __syncthreads();   // previous tile's consumers done with ks/vs/at
        #pragma unroll
        for (int q = 0; q < 4; q++) {      // publish registers -> smem (stride 65)
            int idx = tid + 256 * q;
            int r = idx >> 4, d = (idx & 15) * 4;
            float* pk = &ks[r * 65 + d];
            pk[0] = rk[q].x; pk[1] = rk[q].y; pk[2] = rk[q].z; pk[3] = rk[q].w;
            float* pv = &vs[r * 65 + d];
            pv[0] = rv[q].x; pv[1] = rv[q].y; pv[2] = rv[q].z; pv[3] = rv[q].w;
        }
        __syncthreads();

        if (t < 3) {   // prefetch next tile; LDG latency hides under compute below
            #pragma unroll
            for (int q = 0; q < 4; q++) {
                rk[q] = Kg[1024 * (t + 1) + tid + 256 * q];
                rv[q] = Vg[1024 * (t + 1) + tid + 256 * q];
            }
        }

        if (wi < 7) {   // dots for positions j=c and j=c+32
            float d0 = 0.f, d1 = 0.f;
            const float* qrow = &qs[wi * 64];
            const float* k0 = &ks[c * 65];
            const float* k1 = &ks[(c + 32) * 65];
            #pragma unroll 16
            for (int d = 0; d < 64; d++) {
                float q = qrow[d];
                d0 += q * k0[d];
                d1 += q * k1[d];
            }
            at[wi * 64 + c]      = d0 * 0.125f;
            at[wi * 64 + c + 32] = d1 * 0.125f;
        }
        __syncthreads();

        if (tid < 64) {   // softmax over the 7 slots for position j=tid
            float v[7];
            #pragma unroll
            for (int i = 0; i < 7; i++) v[i] = at[i * 64 + tid];
            float m = v[0];
            #pragma unroll
            for (int i = 1; i < 7; i++) m = fmaxf(m, v[i]);
            float s = 0.f;
            #pragma unroll
            for (int i = 0; i < 7; i++) { v[i] = __expf(v[i] - m); s += v[i]; }
            float inv = 1.f / s;
            #pragma unroll
            for (int i = 0; i < 7; i++) at[i * 64 + tid] = v[i] * inv + ATT_EPS;
        }
        __syncthreads();

        if (wi < 7) {   // accumulate partial updates
            const float* arow = &at[wi * 64];
            #pragma unroll 8
            for (int j = 0; j < 64; j++) {
                float a = arow[j];
                Sa += a;
                U0 += a * vs[j * 65 + c];
                U1 += a * vs[j * 65 + c + 32];
            }
        }
    }

    if (wi < 7) {
        int o = ((b * CH + ch) * 7 + wi) * 64;
        g_Up[o + c]      = U0;
        g_Up[o + c + 32] = U1;
        if (c == 0) g_Sp[(b * CH + ch) * 7 + wi] = Sa;
    }
}

// =================================================================================
// Kernel D: reduce partials + GRU + LN + MLP residual + (next-iter LN + q proj).
// 64 blocks (one per batch), 256 threads, 121 KB dynamic smem for staged weights.
// =================================================================================
__global__ void __launch_bounds__(256) update_kernel(
    const float* __restrict__ W_ih, const float* __restrict__ W_hh,
    const float* __restrict__ b_ih, const float* __restrict__ b_hh,
    const float* __restrict__ W1, const float* __restrict__ b1,
    const float* __restrict__ W2, const float* __restrict__ b2,
    const float* __restrict__ Wq, const float* __restrict__ bq,
    const float* __restrict__ g_sl, const float* __restrict__ be_sl,
    const float* __restrict__ g_ff, const float* __restrict__ be_ff,
    int last, float* __restrict__ out)
{
    extern __shared__ float sm[];
    float* WA  = sm;                 // 192*65  (W_ih, later W1 [128*65], later Wq [64*65])
    float* WB  = WA + 12480;         // 192*65  (W_hh, later W2 [64*129])
    float* upd = WB + 12480;         // 448 (updates, later slot_final)
    float* slp = upd + 448;          // 448
    float* gi  = slp + 448;          // 1344
    float* gh  = gi + 1344;          // 1344
    float* sln = gh + 1344;          // 448
    float* ff  = sln + 448;          // 448
    float* h1  = ff + 448;           // 896
    float* Ssm = h1 + 896;           // 8

    const int tid = threadIdx.x, b = blockIdx.x;
    const int wi = tid >> 5, c = tid & 31;

    for (int i = tid; i < 12288; i += 256) {
        int o = i >> 6, d = i & 63;
        WA[o * 65 + d] = W_ih[i];
        WB[o * 65 + d] = W_hh[i];
    }
    for (int i = tid; i < 448; i += 256) slp[i] = g_slots[b * 448 + i];
    if (tid < 7) {
        float s = 0.f;
        #pragma unroll
        for (int chn = 0; chn < CH; chn++) s += g_Sp[(b * CH + chn) * 7 + tid];
        Ssm[tid] = 1.f / s;
    }
    __syncthreads();

    for (int idx = tid; idx < 448; idx += 256) {   // updates = U / S (fixed order)
        int i = idx >> 6;
        float u = 0.f;
        #pragma unroll
        for (int chn = 0; chn < CH; chn++) u += g_Up[(b * CH + chn) * 448 + idx];
        upd[idx] = u * Ssm[i];
    }
    __syncthreads();

    for (int idx = tid; idx < 1344; idx += 256) {  // GRU gate pre-activations
        int i = idx / 192, o = idx % 192;
        const float* wa = &WA[o * 65];
        const float* wb = &WB[o * 65];
        const float* u = &upd[i * 64];
        const float* h = &slp[i * 64];
        float ai = b_ih[o], ah = b_hh[o];
        #pragma unroll 16
        for (int d = 0; d < 64; d++) { ai += u[d] * wa[d]; ah += h[d] * wb[d]; }
        gi[idx] = ai; gh[idx] = ah;
    }
    __syncthreads();

    for (int idx = tid; idx < 448; idx += 256) {   // GRU combine
        int i = idx >> 6, d = idx & 63;
        float xr = gi[i * 192 + d] + gh[i * 192 + d];
        float xz = gi[i * 192 + 64 + d] + gh[i * 192 + 64 + d];
        float r = 1.f / (1.f + __expf(-xr));
        float z = 1.f / (1.f + __expf(-xz));
        float n = tanhf(gi[i * 192 + 128 + d] + r * gh[i * 192 + 128 + d]);
        sln[idx] = (1.f - z) * n + z * slp[idx];
    }
    __syncthreads();

    if (wi < 7) {   // LN(slots_new) -> ff
        float x0 = sln[wi * 64 + c], x1 = sln[wi * 64 + c + 32];
        float s = x0 + x1, sq = x0 * x0 + x1 * x1;
        #pragma unroll
        for (int o = 16; o > 0; o >>= 1) {
            s  += __shfl_xor_sync(0xffffffffu, s, o);
            sq += __shfl_xor_sync(0xffffffffu, sq, o);
        }
        float m = s * (1.f / 64.f);
        float var = sq * (1.f / 64.f) - m * m;
        float rin = rsqrtf(var + LN_EPS);
        ff[wi * 64 + c]      = (x0 - m) * rin * g_ff[c]      + be_ff[c];
        ff[wi * 64 + c + 32] = (x1 - m) * rin * g_ff[c + 32] + be_ff[c + 32];
    }
    __syncthreads();

    for (int i = tid; i < 8192; i += 256) {        // stage W1 / W2
        WA[(i >> 6) * 65 + (i & 63)] = W1[i];
        WB[(i >> 7) * 129 + (i & 127)] = W2[i];
    }
    __syncthreads();

    for (int idx = tid; idx < 896; idx += 256) {   // h1 = relu(ff@W1^T + b1)
        int i = idx >> 7, h = idx & 127;
        float acc = b1[h];
        const float* f = &ff[i * 64];
        const float* w = &WA[h * 65];
        #pragma unroll 16
        for (int d = 0; d < 64; d++) acc += f[d] * w[d];
        h1[idx] = fmaxf(acc, 0.f);
    }
    __syncthreads();

    for (int idx = tid; idx < 448; idx += 256) {   // out proj + residual
        int i = idx >> 6, d = idx & 63;
        float acc = b2[d];
        const float* hh = &h1[i * 128];
        const float* w = &WB[d * 129];
        #pragma unroll 16
        for (int h = 0; h < 128; h++) acc += hh[h] * w[h];
        float v = sln[idx] + acc;
        g_slots[b * 448 + idx] = v;
        upd[idx] = v;                    // slot_final for q phase
        if (last) out[b * 448 + idx] = v;
    }
    __syncthreads();

    if (!last) {
        for (int i = tid; i < 4096; i += 256) WA[(i >> 6) * 65 + (i & 63)] = Wq[i];
        if (wi < 7) {   // LN(slot_final) with g_sl/be_sl -> ff
            float x0 = upd[wi * 64 + c], x1 = upd[wi * 64 + c + 32];
            float s = x0 + x1, sq = x0 * x0 + x1 * x1;
            #pragma unroll
            for (int o = 16; o > 0; o >>= 1) {
                s  += __shfl_xor_sync(0xffffffffu, s, o);
                sq += __shfl_xor_sync(0xffffffffu, sq, o);
            }
            float m = s * (1.f / 64.f);
            float var = sq * (1.f / 64.f) - m * m;
            float rin = rsqrtf(var + LN_EPS);
            ff[wi * 64 + c]      = (x0 - m) * rin * g_sl[c]      + be_sl[c];
            ff[wi * 64 + c + 32] = (x1 - m) * rin * g_sl[c + 32] + be_sl[c + 32];
        }
        __syncthreads();
        for (int idx = tid; idx < 448; idx += 256) {   // q = s@Wq^T + bq
            int i = idx >> 6, o = idx & 63;
            float acc = bq[o];
            const float* f = &ff[i * 64];
            const float* w = &WA[o * 65];
            #pragma unroll 16
            for (int d = 0; d < 64; d++) acc += f[d] * w[d];
            g_Q[b * 448 + idx] = acc;
        }
    }
}

// =================================================================================
extern "C" void kernel_launch(void* const* d_in, const int* in_sizes, int n_in,
                              void* d_out, int out_size)
{
    const float* inputs = (const float*)d_in[0];
    // d_in[1] = positional_embeddings (unused by reference)
    const float* noise  = (const float*)d_in[2];
    const float* mu     = (const float*)d_in[3];
    const float* sigma  = (const float*)d_in[4];
    const float* Wq     = (const float*)d_in[5];
    const float* bq     = (const float*)d_in[6];
    const float* Wk     = (const float*)d_in[7];
    const float* bk     = (const float*)d_in[8];
    const float* Wv     = (const float*)d_in[9];
    const float* bv     = (const float*)d_in[10];
    const float* W_ih   = (const float*)d_in[11];
    const float* W_hh   = (const float*)d_in[12];
    const float* b_ih   = (const float*)d_in[13];
    const float* b_hh   = (const float*)d_in[14];
    const float* W1     = (const float*)d_in[15];
    const float* b1     = (const float*)d_in[16];
    const float* W2     = (const float*)d_in[17];
    const float* b2     = (const float*)d_in[18];
    const float* g_in   = (const float*)d_in[19];
    const float* be_in  = (const float*)d_in[20];
    const float* g_sl   = (const float*)d_in[21];
    const float* be_sl  = (const float*)d_in[22];
    const float* g_ff   = (const float*)d_in[23];
    const float* be_ff  = (const float*)d_in[24];
    float* out = (float*)d_out;

    const int SMEM_A = 13440 * 4;    // proj_kv
    const int SMEM_D = 30344 * 4;    // update_kernel
    cudaFuncSetAttribute(proj_kv, cudaFuncAttributeMaxDynamicSharedMemorySize, SMEM_A);
    cudaFuncSetAttribute(update_kernel, cudaFuncAttributeMaxDynamicSharedMemorySize, SMEM_D);

    proj_kv<<<(BSZ * NSEQ) / 64, 128, SMEM_A>>>(inputs, Wk, bk, Wv, bv, g_in, be_in);
    init_kernel<<<BSZ, 256>>>(noise, mu, sigma, Wq, bq, g_sl, be_sl);
    for (int it = 0; it < 3; it++) {
        attn_kernel<<<dim3(CH, BSZ), 256>>>();
        update_kernel<<<BSZ, 256, SMEM_D>>>(W_ih, W_hh, b_ih, b_hh, W1, b1, W2, b2,
                                            Wq, bq, g_sl, be_sl, g_ff, be_ff,
                                            (it == 2) ? 1 : 0, out);
    }
}